// round 2
// baseline (speedup 1.0000x reference)
#include <cuda_runtime.h>

#define NN 50000
#define EE 640000
#define GG 500
#define BN_EPS 1e-5f

#define SCAN_CHUNK 1024
#define SCAN_BLOCKS ((NN + SCAN_CHUNK - 1) / SCAN_CHUNK)   // 49

// ---------------- scratch (static device globals; no allocation) ----------------
static __device__ __align__(16) float g_deg[NN];
static __device__ __align__(16) float g_dinv[NN];
static __device__ __align__(16) float g_dinv2[NN];
static __device__ __align__(16) int   g_cnt[NN];
static __device__ __align__(16) int   g_rowptr[NN];
static __device__ __align__(16) int   g_fill[NN];
static __device__ __align__(16) int   g_partial[SCAN_BLOCKS];
static __device__ __align__(16) int   g_csrc[EE];
static __device__ __align__(16) float g_cnorm[EE];
static __device__ __align__(16) float g_s[NN];
static __device__ __align__(16) float g_t[NN * 128];
static __device__ __align__(16) float g_h2[NN * 128];
static __device__ __align__(16) float g_gsum[GG];
static __device__ __align__(16) int   g_gcnt[GG];

// ---------------- kernels ----------------

__global__ void k_zero() {
    int i = blockIdx.x * blockDim.x + threadIdx.x;
    if (i < NN) { g_deg[i] = 0.f; g_cnt[i] = 0; g_fill[i] = 0; }
    if (i < GG) { g_gsum[i] = 0.f; g_gcnt[i] = 0; }
}

// deg[dst] += w  and edge count histogram for CSR
__global__ void k_deg(const int* __restrict__ ei, const float* __restrict__ ea) {
    int e = blockIdx.x * blockDim.x + threadIdx.x;
    if (e >= EE) return;
    int d = ei[EE + e];
    atomicAdd(&g_deg[d], ea[e]);
    atomicAdd(&g_cnt[d], 1);
}

__global__ void k_dinv() {
    int n = blockIdx.x * blockDim.x + threadIdx.x;
    if (n >= NN) return;
    float r = rsqrtf(g_deg[n] + 1.0f);   // +1 self-loop weight
    g_dinv[n]  = r;
    g_dinv2[n] = r * r;
}

// ---- hierarchical exclusive scan over g_cnt -> g_rowptr ----
// pass 1: each block scans a chunk of SCAN_CHUNK, writes local-exclusive scan
//         into g_rowptr and the block total into g_partial.
__global__ __launch_bounds__(256) void k_scan1() {
    __shared__ int tsum[256];
    const int tid = threadIdx.x;
    const int base = blockIdx.x * SCAN_CHUNK;
    // each thread: 4 consecutive values
    int idx0 = base + tid * 4;
    int c0 = 0, c1 = 0, c2 = 0, c3 = 0;
    if (idx0 + 0 < NN) c0 = g_cnt[idx0 + 0];
    if (idx0 + 1 < NN) c1 = g_cnt[idx0 + 1];
    if (idx0 + 2 < NN) c2 = g_cnt[idx0 + 2];
    if (idx0 + 3 < NN) c3 = g_cnt[idx0 + 3];
    int mysum = c0 + c1 + c2 + c3;

    // warp inclusive scan of thread sums
    const int lane = tid & 31;
    const int wid = tid >> 5;
    int v = mysum;
#pragma unroll
    for (int off = 1; off < 32; off <<= 1) {
        int u = __shfl_up_sync(0xffffffffu, v, off);
        if (lane >= off) v += u;
    }
    __shared__ int wsum[8];
    if (lane == 31) wsum[wid] = v;
    __syncthreads();
    if (wid == 0) {
        int w = (lane < 8) ? wsum[lane] : 0;
#pragma unroll
        for (int off = 1; off < 8; off <<= 1) {
            int u = __shfl_up_sync(0xffffffffu, w, off);
            if (lane >= off) w += u;
        }
        if (lane < 8) wsum[lane] = w;
    }
    __syncthreads();
    int excl = v - mysum + ((wid > 0) ? wsum[wid - 1] : 0);

    if (idx0 + 0 < NN) g_rowptr[idx0 + 0] = excl;
    if (idx0 + 1 < NN) g_rowptr[idx0 + 1] = excl + c0;
    if (idx0 + 2 < NN) g_rowptr[idx0 + 2] = excl + c0 + c1;
    if (idx0 + 3 < NN) g_rowptr[idx0 + 3] = excl + c0 + c1 + c2;

    if (tid == 255) g_partial[blockIdx.x] = excl + mysum;   // block total
}

// pass 2: single warp scans the 49 block totals (exclusive)
__global__ void k_scan2() {
    const int lane = threadIdx.x;
    int v = (lane < SCAN_BLOCKS) ? g_partial[lane] : 0;
    int incl = v;
#pragma unroll
    for (int off = 1; off < 32; off <<= 1) {
        int u = __shfl_up_sync(0xffffffffu, incl, off);
        if (lane >= off) incl += u;
    }
    // handle >32 partials: lanes 32.. not present (blockDim=64 would need more);
    // SCAN_BLOCKS=49 > 32, so use 64 threads with smem
    __shared__ int sh[64];
    sh[lane] = v;
    __syncthreads();
    if (lane == 0) {
        int run = 0;
        for (int i = 0; i < SCAN_BLOCKS; i++) { int c = sh[i]; sh[i] = run; run += c; }
    }
    __syncthreads();
    if (lane < SCAN_BLOCKS) g_partial[lane] = sh[lane];
}

// pass 3: add block offsets
__global__ __launch_bounds__(256) void k_scan3() {
    const int base = blockIdx.x * SCAN_CHUNK;
    const int off = g_partial[blockIdx.x];
    int i = base + threadIdx.x * 4;
#pragma unroll
    for (int j = 0; j < 4; j++)
        if (i + j < NN) g_rowptr[i + j] += off;
}

// build CSR: src index + precomputed norm = dinv[src]*w*dinv[dst]
__global__ void k_scatter(const int* __restrict__ ei, const float* __restrict__ ea) {
    int e = blockIdx.x * blockDim.x + threadIdx.x;
    if (e >= EE) return;
    int s = ei[e];
    int d = ei[EE + e];
    float w = ea[e];
    int pos = g_rowptr[d] + atomicAdd(&g_fill[d], 1);
    g_csrc[pos]  = s;
    g_cnorm[pos] = g_dinv[s] * w * g_dinv[d];
}

// layer-1: scalar aggregation (input dim = 1), plus per-graph node counts
__global__ void k_l1_agg(const float* __restrict__ x, const int* __restrict__ batch) {
    int n = blockIdx.x * blockDim.x + threadIdx.x;
    if (n >= NN) return;
    int beg = g_rowptr[n], end = beg + g_cnt[n];
    float acc = 0.f;
    for (int e = beg; e < end; e++)
        acc += g_cnorm[e] * __ldg(&x[g_csrc[e]]);
    acc += g_dinv2[n] * x[n];
    g_s[n] = acc;
    atomicAdd(&g_gcnt[batch[n]], 1);
}

// SIMT GEMM layer-2: t[N,128] = h1[N,64] @ W2, where h1 is computed on the fly:
//   h1[n,f] = relu(s[n]*A1[f] + C1[f]),  A1[f]=W1[f]*sc[f], C1[f]=b1[f]*sc[f]+sh[f]
__global__ __launch_bounds__(128) void k_gemm1(
    const float* __restrict__ W,
    const float* __restrict__ W1, const float* __restrict__ b1,
    const float* __restrict__ g1, const float* __restrict__ be1,
    const float* __restrict__ m1, const float* __restrict__ v1) {

    constexpr int K = 64;
    float* __restrict__ Out = g_t;

    __shared__ float Wsh[32 * 128];
    __shared__ float Hsh[32 * K];
    __shared__ float A1[64], C1[64];

    const int tid = threadIdx.x;
    const int nb = blockIdx.x * 32;

    if (tid < 64) {
        float sc = g1[tid] * rsqrtf(v1[tid] + BN_EPS);
        float sh = be1[tid] - m1[tid] * sc;
        A1[tid] = W1[tid] * sc;
        C1[tid] = fmaf(b1[tid], sc, sh);
    }
    __syncthreads();

    // build H tile from scalar s
    for (int i = tid; i < 32 * K; i += 128) {
        int mrow = i / K, k = i % K;
        int n = nb + mrow;
        float s = (n < NN) ? g_s[n] : 0.f;
        Hsh[i] = fmaxf(fmaf(s, A1[k], C1[k]), 0.f);
    }

    const int fq = tid & 31;
    const int mo = tid >> 5;
    float acc[8][4];
#pragma unroll
    for (int j = 0; j < 8; j++) { acc[j][0] = acc[j][1] = acc[j][2] = acc[j][3] = 0.f; }

    const float* hb = &Hsh[(mo * 8) * K];

    for (int kk = 0; kk < K; kk += 32) {
        __syncthreads();
        for (int i = tid; i < 32 * 128; i += 128) Wsh[i] = W[kk * 128 + i];
        __syncthreads();
#pragma unroll 8
        for (int k2 = 0; k2 < 32; k2++) {
            float4 w = *(const float4*)&Wsh[k2 * 128 + fq * 4];
            int k = kk + k2;
#pragma unroll
            for (int j = 0; j < 8; j++) {
                float h = hb[j * K + k];
                acc[j][0] = fmaf(h, w.x, acc[j][0]);
                acc[j][1] = fmaf(h, w.y, acc[j][1]);
                acc[j][2] = fmaf(h, w.z, acc[j][2]);
                acc[j][3] = fmaf(h, w.w, acc[j][3]);
            }
        }
    }

#pragma unroll
    for (int j = 0; j < 8; j++) {
        int n = nb + mo * 8 + j;
        if (n < NN)
            *(float4*)&Out[n * 128 + fq * 4] =
                make_float4(acc[j][0], acc[j][1], acc[j][2], acc[j][3]);
    }
}

// SIMT GEMM layer-3: t[N,128] = h2[N,128] @ W3
__global__ __launch_bounds__(128) void k_gemm2(const float* __restrict__ W) {
    constexpr int K = 128;
    const float* __restrict__ A = g_h2;
    float* __restrict__ Out = g_t;

    __shared__ float Wsh[32 * 128];
    __shared__ float Hsh[32 * K];

    const int tid = threadIdx.x;
    const int nb = blockIdx.x * 32;

    for (int i = tid; i < 32 * K; i += 128) {
        int mrow = i / K, k = i % K;
        int n = nb + mrow;
        Hsh[i] = (n < NN) ? A[n * K + k] : 0.f;
    }

    const int fq = tid & 31;
    const int mo = tid >> 5;
    float acc[8][4];
#pragma unroll
    for (int j = 0; j < 8; j++) { acc[j][0] = acc[j][1] = acc[j][2] = acc[j][3] = 0.f; }

    const float* hb = &Hsh[(mo * 8) * K];

    for (int kk = 0; kk < K; kk += 32) {
        __syncthreads();
        for (int i = tid; i < 32 * 128; i += 128) Wsh[i] = W[kk * 128 + i];
        __syncthreads();
#pragma unroll 8
        for (int k2 = 0; k2 < 32; k2++) {
            float4 w = *(const float4*)&Wsh[k2 * 128 + fq * 4];
            int k = kk + k2;
#pragma unroll
            for (int j = 0; j < 8; j++) {
                float h = hb[j * K + k];
                acc[j][0] = fmaf(h, w.x, acc[j][0]);
                acc[j][1] = fmaf(h, w.y, acc[j][1]);
                acc[j][2] = fmaf(h, w.z, acc[j][2]);
                acc[j][3] = fmaf(h, w.w, acc[j][3]);
            }
        }
    }

#pragma unroll
    for (int j = 0; j < 8; j++) {
        int n = nb + mo * 8 + j;
        if (n < NN)
            *(float4*)&Out[n * 128 + fq * 4] =
                make_float4(acc[j][0], acc[j][1], acc[j][2], acc[j][3]);
    }
}

// CSR gather for F=128: one warp per node, lane handles 4 features (float4).
template<bool FINAL>
__global__ __launch_bounds__(256) void k_gather(
    const float* __restrict__ b, const float* __restrict__ g,
    const float* __restrict__ be, const float* __restrict__ m,
    const float* __restrict__ v, const float* __restrict__ Wf,
    const int* __restrict__ batch) {

    const float* __restrict__ t = g_t;
    int wid = (blockIdx.x * blockDim.x + threadIdx.x) >> 5;
    int lane = threadIdx.x & 31;
    if (wid >= NN) return;
    int n = wid;

    int beg = g_rowptr[n], end = beg + g_cnt[n];
    float ax = 0.f, ay = 0.f, az = 0.f, aw = 0.f;
    for (int e = beg; e < end; e++) {
        int s = g_csrc[e];
        float nm = g_cnorm[e];
        float4 tv = *(const float4*)&t[s * 128 + lane * 4];
        ax = fmaf(nm, tv.x, ax);
        ay = fmaf(nm, tv.y, ay);
        az = fmaf(nm, tv.z, az);
        aw = fmaf(nm, tv.w, aw);
    }
    float di = g_dinv2[n];
    float4 tn = *(const float4*)&t[n * 128 + lane * 4];
    ax = fmaf(di, tn.x, ax);
    ay = fmaf(di, tn.y, ay);
    az = fmaf(di, tn.z, az);
    aw = fmaf(di, tn.w, aw);

    float4 b4  = *(const float4*)&b[lane * 4];
    float4 g4  = *(const float4*)&g[lane * 4];
    float4 be4 = *(const float4*)&be[lane * 4];
    float4 m4  = *(const float4*)&m[lane * 4];
    float4 v4  = *(const float4*)&v[lane * 4];

    float scx = g4.x * rsqrtf(v4.x + BN_EPS);
    float scy = g4.y * rsqrtf(v4.y + BN_EPS);
    float scz = g4.z * rsqrtf(v4.z + BN_EPS);
    float scw = g4.w * rsqrtf(v4.w + BN_EPS);
    float rx = fmaxf(fmaf(ax + b4.x - m4.x, scx, be4.x), 0.f);
    float ry = fmaxf(fmaf(ay + b4.y - m4.y, scy, be4.y), 0.f);
    float rz = fmaxf(fmaf(az + b4.z - m4.z, scz, be4.z), 0.f);
    float rw = fmaxf(fmaf(aw + b4.w - m4.w, scw, be4.w), 0.f);

    if (FINAL) {
        float4 r4 = *(const float4*)&g_h2[n * 128 + lane * 4];
        rx += r4.x; ry += r4.y; rz += r4.z; rw += r4.w;
        float4 wf = *(const float4*)&Wf[lane * 4];
        float y = rx * wf.x + ry * wf.y + rz * wf.z + rw * wf.w;
#pragma unroll
        for (int off = 16; off; off >>= 1) y += __shfl_xor_sync(0xffffffffu, y, off);
        if (lane == 0) atomicAdd(&g_gsum[batch[n]], y);
    } else {
        *(float4*)&g_h2[n * 128 + lane * 4] = make_float4(rx, ry, rz, rw);
    }
}

__global__ void k_out(const float* __restrict__ bf, float* __restrict__ out) {
    int gidx = blockIdx.x * blockDim.x + threadIdx.x;
    if (gidx >= GG) return;
    out[gidx] = g_gsum[gidx] / fmaxf((float)g_gcnt[gidx], 1.f) + bf[0];
}

// ---------------- launch ----------------
extern "C" void kernel_launch(void* const* d_in, const int* in_sizes, int n_in,
                              void* d_out, int out_size) {
    const float* x   = (const float*)d_in[0];
    const int*   ei  = (const int*)d_in[1];
    const float* ea  = (const float*)d_in[2];
    const int*   bat = (const int*)d_in[3];
    const float* W1  = (const float*)d_in[4];
    const float* b1  = (const float*)d_in[5];
    const float* W2  = (const float*)d_in[6];
    const float* b2  = (const float*)d_in[7];
    const float* W3  = (const float*)d_in[8];
    const float* b3  = (const float*)d_in[9];
    const float* Wf  = (const float*)d_in[10];
    const float* bf  = (const float*)d_in[11];
    const float* g1  = (const float*)d_in[12];
    const float* be1 = (const float*)d_in[13];
    const float* m1  = (const float*)d_in[14];
    const float* v1  = (const float*)d_in[15];
    const float* g2  = (const float*)d_in[16];
    const float* be2 = (const float*)d_in[17];
    const float* m2  = (const float*)d_in[18];
    const float* v2  = (const float*)d_in[19];
    const float* g3  = (const float*)d_in[20];
    const float* be3 = (const float*)d_in[21];
    const float* m3  = (const float*)d_in[22];
    const float* v3  = (const float*)d_in[23];
    float* out = (float*)d_out;

    k_zero<<<(NN + 255) / 256, 256>>>();
    k_deg<<<(EE + 255) / 256, 256>>>(ei, ea);
    k_dinv<<<(NN + 255) / 256, 256>>>();
    k_scan1<<<SCAN_BLOCKS, 256>>>();
    k_scan2<<<1, 64>>>();
    k_scan3<<<SCAN_BLOCKS, 256>>>();
    k_scatter<<<(EE + 255) / 256, 256>>>(ei, ea);

    // layer 1 (scalar agg; BN/relu fused into gemm1 A-load)
    k_l1_agg<<<(NN + 255) / 256, 256>>>(x, bat);

    // layer 2: t = relu(bn(s*W1+b1)) @ W2 ; gather -> h2 (residual)
    k_gemm1<<<(NN + 31) / 32, 128>>>(W2, W1, b1, g1, be1, m1, v1);
    k_gather<false><<<(NN * 32 + 255) / 256, 256>>>(b2, g2, be2, m2, v2, Wf, bat);

    // layer 3: t = h2 @ W3 ; gather + residual + Wf dot + graph pool (fused)
    k_gemm2<<<(NN + 31) / 32, 128>>>(W3);
    k_gather<true><<<(NN * 32 + 255) / 256, 256>>>(b3, g3, be3, m3, v3, Wf, bat);

    k_out<<<(GG + 255) / 256, 256>>>(bf, out);
}

// round 3
// speedup vs baseline: 1.6096x; 1.6096x over previous
#include <cuda_runtime.h>
#include <cuda_fp16.h>

#define NN 50000
#define EE 640000
#define GG 500
#define BN_EPS 1e-5f

#define SCAN_CHUNK 1024
#define SCAN_BLOCKS ((NN + SCAN_CHUNK - 1) / SCAN_CHUNK)   // 49

// ---------------- scratch (static device globals; no allocation) ----------------
static __device__ __align__(16) float  g_deg[NN];
static __device__ __align__(16) float  g_dinv[NN];
static __device__ __align__(16) float  g_dinv2[NN];
static __device__ __align__(16) int    g_cnt[NN];
static __device__ __align__(16) int    g_rowptr[NN];
static __device__ __align__(16) int    g_fill[NN];
static __device__ __align__(16) int    g_partial[SCAN_BLOCKS];
static __device__ __align__(16) int    g_csrc[EE];
static __device__ __align__(16) float  g_cnorm[EE];
static __device__ __align__(16) float  g_s[NN];
static __device__ __align__(16) __half g_t[NN * 128];     // fp16 transformed features
static __device__ __align__(16) float  g_h2[NN * 128];
static __device__ __align__(16) float  g_gsum[GG];
static __device__ __align__(16) int    g_gcnt[GG];

// ---------------- kernels ----------------

__global__ void k_zero() {
    int i = blockIdx.x * blockDim.x + threadIdx.x;
    if (i < NN) { g_deg[i] = 0.f; g_cnt[i] = 0; g_fill[i] = 0; }
    if (i < GG) { g_gsum[i] = 0.f; g_gcnt[i] = 0; }
}

__global__ void k_deg(const int* __restrict__ ei, const float* __restrict__ ea) {
    int e = blockIdx.x * blockDim.x + threadIdx.x;
    if (e >= EE) return;
    int d = ei[EE + e];
    atomicAdd(&g_deg[d], ea[e]);
    atomicAdd(&g_cnt[d], 1);
}

__global__ void k_dinv() {
    int n = blockIdx.x * blockDim.x + threadIdx.x;
    if (n >= NN) return;
    float r = rsqrtf(g_deg[n] + 1.0f);   // +1 self-loop weight
    g_dinv[n]  = r;
    g_dinv2[n] = r * r;
}

// ---- hierarchical exclusive scan over g_cnt -> g_rowptr ----
__global__ __launch_bounds__(256) void k_scan1() {
    const int tid = threadIdx.x;
    const int base = blockIdx.x * SCAN_CHUNK;
    int idx0 = base + tid * 4;
    int c0 = 0, c1 = 0, c2 = 0, c3 = 0;
    if (idx0 + 0 < NN) c0 = g_cnt[idx0 + 0];
    if (idx0 + 1 < NN) c1 = g_cnt[idx0 + 1];
    if (idx0 + 2 < NN) c2 = g_cnt[idx0 + 2];
    if (idx0 + 3 < NN) c3 = g_cnt[idx0 + 3];
    int mysum = c0 + c1 + c2 + c3;

    const int lane = tid & 31;
    const int wid = tid >> 5;
    int v = mysum;
#pragma unroll
    for (int off = 1; off < 32; off <<= 1) {
        int u = __shfl_up_sync(0xffffffffu, v, off);
        if (lane >= off) v += u;
    }
    __shared__ int wsum[8];
    if (lane == 31) wsum[wid] = v;
    __syncthreads();
    if (wid == 0) {
        int w = (lane < 8) ? wsum[lane] : 0;
#pragma unroll
        for (int off = 1; off < 8; off <<= 1) {
            int u = __shfl_up_sync(0xffffffffu, w, off);
            if (lane >= off) w += u;
        }
        if (lane < 8) wsum[lane] = w;
    }
    __syncthreads();
    int excl = v - mysum + ((wid > 0) ? wsum[wid - 1] : 0);

    if (idx0 + 0 < NN) g_rowptr[idx0 + 0] = excl;
    if (idx0 + 1 < NN) g_rowptr[idx0 + 1] = excl + c0;
    if (idx0 + 2 < NN) g_rowptr[idx0 + 2] = excl + c0 + c1;
    if (idx0 + 3 < NN) g_rowptr[idx0 + 3] = excl + c0 + c1 + c2;

    if (tid == 255) g_partial[blockIdx.x] = excl + mysum;
}

__global__ void k_scan2() {
    const int lane = threadIdx.x;
    __shared__ int sh[64];
    sh[lane] = (lane < SCAN_BLOCKS) ? g_partial[lane] : 0;
    __syncthreads();
    if (lane == 0) {
        int run = 0;
        for (int i = 0; i < SCAN_BLOCKS; i++) { int c = sh[i]; sh[i] = run; run += c; }
    }
    __syncthreads();
    if (lane < SCAN_BLOCKS) g_partial[lane] = sh[lane];
}

__global__ __launch_bounds__(256) void k_scan3() {
    const int base = blockIdx.x * SCAN_CHUNK;
    const int off = g_partial[blockIdx.x];
    int i = base + threadIdx.x * 4;
#pragma unroll
    for (int j = 0; j < 4; j++)
        if (i + j < NN) g_rowptr[i + j] += off;
}

// build CSR: src index + precomputed norm = dinv[src]*w*dinv[dst]
__global__ void k_scatter(const int* __restrict__ ei, const float* __restrict__ ea) {
    int e = blockIdx.x * blockDim.x + threadIdx.x;
    if (e >= EE) return;
    int s = ei[e];
    int d = ei[EE + e];
    float w = ea[e];
    int pos = g_rowptr[d] + atomicAdd(&g_fill[d], 1);
    g_csrc[pos]  = s;
    g_cnorm[pos] = g_dinv[s] * w * g_dinv[d];
}

// layer-1: scalar aggregation (input dim = 1), plus per-graph node counts
__global__ void k_l1_agg(const float* __restrict__ x, const int* __restrict__ batch) {
    int n = blockIdx.x * blockDim.x + threadIdx.x;
    if (n >= NN) return;
    int beg = g_rowptr[n], end = beg + g_cnt[n];
    float acc = 0.f;
    for (int e = beg; e < end; e++)
        acc += g_cnorm[e] * __ldg(&x[g_csrc[e]]);
    acc += g_dinv2[n] * x[n];
    g_s[n] = acc;
    atomicAdd(&g_gcnt[batch[n]], 1);
}

// ---- GEMM epilogue: fp32 acc -> 4 halves (8B store) ----
__device__ __forceinline__ void store_t_half4(int n, int fq,
                                              float a0, float a1, float a2, float a3) {
    __half2 h0 = __floats2half2_rn(a0, a1);
    __half2 h1 = __floats2half2_rn(a2, a3);
    uint2 st;
    st.x = *(unsigned int*)&h0;
    st.y = *(unsigned int*)&h1;
    *(uint2*)&g_t[n * 128 + fq * 4] = st;
}

// SIMT GEMM layer-2: t[N,128] = h1[N,64] @ W2, h1 built on the fly:
//   h1[n,f] = relu(s[n]*A1[f] + C1[f])
__global__ __launch_bounds__(128) void k_gemm1(
    const float* __restrict__ W,
    const float* __restrict__ W1, const float* __restrict__ b1,
    const float* __restrict__ g1, const float* __restrict__ be1,
    const float* __restrict__ m1, const float* __restrict__ v1) {

    constexpr int K = 64;
    __shared__ float Wsh[32 * 128];
    __shared__ float Hsh[32 * K];
    __shared__ float A1[64], C1[64];

    const int tid = threadIdx.x;
    const int nb = blockIdx.x * 32;

    if (tid < 64) {
        float sc = g1[tid] * rsqrtf(v1[tid] + BN_EPS);
        float sh = be1[tid] - m1[tid] * sc;
        A1[tid] = W1[tid] * sc;
        C1[tid] = fmaf(b1[tid], sc, sh);
    }
    __syncthreads();

    for (int i = tid; i < 32 * K; i += 128) {
        int mrow = i / K, k = i % K;
        int n = nb + mrow;
        float s = (n < NN) ? g_s[n] : 0.f;
        Hsh[i] = fmaxf(fmaf(s, A1[k], C1[k]), 0.f);
    }

    const int fq = tid & 31;
    const int mo = tid >> 5;
    float acc[8][4];
#pragma unroll
    for (int j = 0; j < 8; j++) { acc[j][0] = acc[j][1] = acc[j][2] = acc[j][3] = 0.f; }

    const float* hb = &Hsh[(mo * 8) * K];

    for (int kk = 0; kk < K; kk += 32) {
        __syncthreads();
        for (int i = tid; i < 32 * 128; i += 128) Wsh[i] = W[kk * 128 + i];
        __syncthreads();
#pragma unroll 8
        for (int k2 = 0; k2 < 32; k2++) {
            float4 w = *(const float4*)&Wsh[k2 * 128 + fq * 4];
            int k = kk + k2;
#pragma unroll
            for (int j = 0; j < 8; j++) {
                float h = hb[j * K + k];
                acc[j][0] = fmaf(h, w.x, acc[j][0]);
                acc[j][1] = fmaf(h, w.y, acc[j][1]);
                acc[j][2] = fmaf(h, w.z, acc[j][2]);
                acc[j][3] = fmaf(h, w.w, acc[j][3]);
            }
        }
    }

#pragma unroll
    for (int j = 0; j < 8; j++) {
        int n = nb + mo * 8 + j;
        if (n < NN) store_t_half4(n, fq, acc[j][0], acc[j][1], acc[j][2], acc[j][3]);
    }
}

// SIMT GEMM layer-3: t[N,128] = h2[N,128] @ W3
__global__ __launch_bounds__(128) void k_gemm2(const float* __restrict__ W) {
    constexpr int K = 128;
    const float* __restrict__ A = g_h2;

    __shared__ float Wsh[32 * 128];
    __shared__ float Hsh[32 * K];

    const int tid = threadIdx.x;
    const int nb = blockIdx.x * 32;

    for (int i = tid; i < 32 * K; i += 128) {
        int mrow = i / K, k = i % K;
        int n = nb + mrow;
        Hsh[i] = (n < NN) ? A[n * K + k] : 0.f;
    }

    const int fq = tid & 31;
    const int mo = tid >> 5;
    float acc[8][4];
#pragma unroll
    for (int j = 0; j < 8; j++) { acc[j][0] = acc[j][1] = acc[j][2] = acc[j][3] = 0.f; }

    const float* hb = &Hsh[(mo * 8) * K];

    for (int kk = 0; kk < K; kk += 32) {
        __syncthreads();
        for (int i = tid; i < 32 * 128; i += 128) Wsh[i] = W[kk * 128 + i];
        __syncthreads();
#pragma unroll 8
        for (int k2 = 0; k2 < 32; k2++) {
            float4 w = *(const float4*)&Wsh[k2 * 128 + fq * 4];
            int k = kk + k2;
#pragma unroll
            for (int j = 0; j < 8; j++) {
                float h = hb[j * K + k];
                acc[j][0] = fmaf(h, w.x, acc[j][0]);
                acc[j][1] = fmaf(h, w.y, acc[j][1]);
                acc[j][2] = fmaf(h, w.z, acc[j][2]);
                acc[j][3] = fmaf(h, w.w, acc[j][3]);
            }
        }
    }

#pragma unroll
    for (int j = 0; j < 8; j++) {
        int n = nb + mo * 8 + j;
        if (n < NN) store_t_half4(n, fq, acc[j][0], acc[j][1], acc[j][2], acc[j][3]);
    }
}

// CSR gather for F=128 over fp16 t: one warp per node, lane holds 4 features (8B loads).
template<bool FINAL>
__global__ __launch_bounds__(256) void k_gather(
    const float* __restrict__ b, const float* __restrict__ g,
    const float* __restrict__ be, const float* __restrict__ m,
    const float* __restrict__ v, const float* __restrict__ Wf,
    const int* __restrict__ batch) {

    int wid = (blockIdx.x * blockDim.x + threadIdx.x) >> 5;
    int lane = threadIdx.x & 31;
    if (wid >= NN) return;
    int n = wid;

    int beg = g_rowptr[n], end = beg + g_cnt[n];
    float ax = 0.f, ay = 0.f, az = 0.f, aw = 0.f;
    for (int e = beg; e < end; e++) {
        int s = g_csrc[e];
        float nm = g_cnorm[e];
        uint2 raw = *(const uint2*)&g_t[s * 128 + lane * 4];
        float2 f0 = __half22float2(*(__half2*)&raw.x);
        float2 f1 = __half22float2(*(__half2*)&raw.y);
        ax = fmaf(nm, f0.x, ax);
        ay = fmaf(nm, f0.y, ay);
        az = fmaf(nm, f1.x, az);
        aw = fmaf(nm, f1.y, aw);
    }
    float di = g_dinv2[n];
    {
        uint2 raw = *(const uint2*)&g_t[n * 128 + lane * 4];
        float2 f0 = __half22float2(*(__half2*)&raw.x);
        float2 f1 = __half22float2(*(__half2*)&raw.y);
        ax = fmaf(di, f0.x, ax);
        ay = fmaf(di, f0.y, ay);
        az = fmaf(di, f1.x, az);
        aw = fmaf(di, f1.y, aw);
    }

    float4 b4  = *(const float4*)&b[lane * 4];
    float4 g4  = *(const float4*)&g[lane * 4];
    float4 be4 = *(const float4*)&be[lane * 4];
    float4 m4  = *(const float4*)&m[lane * 4];
    float4 v4  = *(const float4*)&v[lane * 4];

    float scx = g4.x * rsqrtf(v4.x + BN_EPS);
    float scy = g4.y * rsqrtf(v4.y + BN_EPS);
    float scz = g4.z * rsqrtf(v4.z + BN_EPS);
    float scw = g4.w * rsqrtf(v4.w + BN_EPS);
    float rx = fmaxf(fmaf(ax + b4.x - m4.x, scx, be4.x), 0.f);
    float ry = fmaxf(fmaf(ay + b4.y - m4.y, scy, be4.y), 0.f);
    float rz = fmaxf(fmaf(az + b4.z - m4.z, scz, be4.z), 0.f);
    float rw = fmaxf(fmaf(aw + b4.w - m4.w, scw, be4.w), 0.f);

    if (FINAL) {
        float4 r4 = *(const float4*)&g_h2[n * 128 + lane * 4];
        rx += r4.x; ry += r4.y; rz += r4.z; rw += r4.w;
        float4 wf = *(const float4*)&Wf[lane * 4];
        float y = rx * wf.x + ry * wf.y + rz * wf.z + rw * wf.w;
#pragma unroll
        for (int off = 16; off; off >>= 1) y += __shfl_xor_sync(0xffffffffu, y, off);
        if (lane == 0) atomicAdd(&g_gsum[batch[n]], y);
    } else {
        *(float4*)&g_h2[n * 128 + lane * 4] = make_float4(rx, ry, rz, rw);
    }
}

__global__ void k_out(const float* __restrict__ bf, float* __restrict__ out) {
    int gidx = blockIdx.x * blockDim.x + threadIdx.x;
    if (gidx >= GG) return;
    out[gidx] = g_gsum[gidx] / fmaxf((float)g_gcnt[gidx], 1.f) + bf[0];
}

// ---------------- launch ----------------
extern "C" void kernel_launch(void* const* d_in, const int* in_sizes, int n_in,
                              void* d_out, int out_size) {
    const float* x   = (const float*)d_in[0];
    const int*   ei  = (const int*)d_in[1];
    const float* ea  = (const float*)d_in[2];
    const int*   bat = (const int*)d_in[3];
    const float* W1  = (const float*)d_in[4];
    const float* b1  = (const float*)d_in[5];
    const float* W2  = (const float*)d_in[6];
    const float* b2  = (const float*)d_in[7];
    const float* W3  = (const float*)d_in[8];
    const float* b3  = (const float*)d_in[9];
    const float* Wf  = (const float*)d_in[10];
    const float* bf  = (const float*)d_in[11];
    const float* g1  = (const float*)d_in[12];
    const float* be1 = (const float*)d_in[13];
    const float* m1  = (const float*)d_in[14];
    const float* v1  = (const float*)d_in[15];
    const float* g2  = (const float*)d_in[16];
    const float* be2 = (const float*)d_in[17];
    const float* m2  = (const float*)d_in[18];
    const float* v2  = (const float*)d_in[19];
    const float* g3  = (const float*)d_in[20];
    const float* be3 = (const float*)d_in[21];
    const float* m3  = (const float*)d_in[22];
    const float* v3  = (const float*)d_in[23];
    float* out = (float*)d_out;

    k_zero<<<(NN + 255) / 256, 256>>>();
    k_deg<<<(EE + 255) / 256, 256>>>(ei, ea);
    k_dinv<<<(NN + 255) / 256, 256>>>();
    k_scan1<<<SCAN_BLOCKS, 256>>>();
    k_scan2<<<1, 64>>>();
    k_scan3<<<SCAN_BLOCKS, 256>>>();
    k_scatter<<<(EE + 255) / 256, 256>>>(ei, ea);

    k_l1_agg<<<(NN + 255) / 256, 256>>>(x, bat);

    k_gemm1<<<(NN + 31) / 32, 128>>>(W2, W1, b1, g1, be1, m1, v1);
    k_gather<false><<<(NN * 32 + 255) / 256, 256>>>(b2, g2, be2, m2, v2, Wf, bat);

    k_gemm2<<<(NN + 31) / 32, 128>>>(W3);
    k_gather<true><<<(NN * 32 + 255) / 256, 256>>>(b3, g3, be3, m3, v3, Wf, bat);

    k_out<<<(GG + 255) / 256, 256>>>(bf, out);
}

// round 4
// speedup vs baseline: 2.3367x; 1.4517x over previous
#include <cuda_runtime.h>
#include <cuda_fp16.h>

#define NN 50000
#define EE 640000
#define GG 500
#define BN_EPS 1e-5f

#define SCAN_CHUNK 1024
#define SCAN_BLOCKS ((NN + SCAN_CHUNK - 1) / SCAN_CHUNK)   // 49

// ---------------- scratch (static device globals; no allocation) ----------------
static __device__ __align__(16) float  g_deg[NN];
static __device__ __align__(16) float  g_dinv[NN];
static __device__ __align__(16) float  g_dinv2[NN];
static __device__ __align__(16) int    g_cnt[NN];
static __device__ __align__(16) int    g_rowptr[NN];
static __device__ __align__(16) int    g_fill[NN];
static __device__ __align__(16) int    g_partial[SCAN_BLOCKS];
static __device__ __align__(16) int    g_csrc[EE];
static __device__ __align__(16) float  g_cnorm[EE];
static __device__ __align__(16) float  g_s[NN];
static __device__ __align__(16) __half g_h1h[NN * 64];    // fp16 layer-1 output
static __device__ __align__(16) __half g_t[NN * 128];     // fp16 transformed features
static __device__ __align__(16) __half g_h2h[NN * 128];   // fp16 layer-2 output (residual + gemm A)
static __device__ __align__(16) __half g_wt2[128 * 64];   // W2^T fp16 [n][k]
static __device__ __align__(16) __half g_wt3[128 * 128];  // W3^T fp16 [n][k]
static __device__ __align__(16) float  g_gsum[GG];
static __device__ __align__(16) int    g_gcnt[GG];

// ---------------- setup kernels ----------------

__global__ void k_zero() {
    int i = blockIdx.x * blockDim.x + threadIdx.x;
    if (i < NN) { g_deg[i] = 0.f; g_cnt[i] = 0; g_fill[i] = 0; }
    if (i < GG) { g_gsum[i] = 0.f; g_gcnt[i] = 0; }
}

__global__ void k_deg(const int* __restrict__ ei, const float* __restrict__ ea) {
    int e = blockIdx.x * blockDim.x + threadIdx.x;
    if (e >= EE) return;
    int d = ei[EE + e];
    atomicAdd(&g_deg[d], ea[e]);
    atomicAdd(&g_cnt[d], 1);
}

__global__ void k_dinv() {
    int n = blockIdx.x * blockDim.x + threadIdx.x;
    if (n >= NN) return;
    float r = rsqrtf(g_deg[n] + 1.0f);   // +1 self-loop weight
    g_dinv[n]  = r;
    g_dinv2[n] = r * r;
}

// transpose + fp16-convert weights: wt[n][k] = W[k][n]
__global__ void k_prep_w(const float* __restrict__ W2, const float* __restrict__ W3) {
    int i = blockIdx.x * blockDim.x + threadIdx.x;
    if (i < 128 * 64) {
        int n = i / 64, k = i % 64;
        g_wt2[i] = __float2half(W2[k * 128 + n]);
    }
    if (i < 128 * 128) {
        int n = i / 128, k = i % 128;
        g_wt3[i] = __float2half(W3[k * 128 + n]);
    }
}

// ---- hierarchical exclusive scan over g_cnt -> g_rowptr ----
__global__ __launch_bounds__(256) void k_scan1() {
    const int tid = threadIdx.x;
    const int base = blockIdx.x * SCAN_CHUNK;
    int idx0 = base + tid * 4;
    int c0 = 0, c1 = 0, c2 = 0, c3 = 0;
    if (idx0 + 0 < NN) c0 = g_cnt[idx0 + 0];
    if (idx0 + 1 < NN) c1 = g_cnt[idx0 + 1];
    if (idx0 + 2 < NN) c2 = g_cnt[idx0 + 2];
    if (idx0 + 3 < NN) c3 = g_cnt[idx0 + 3];
    int mysum = c0 + c1 + c2 + c3;

    const int lane = tid & 31;
    const int wid = tid >> 5;
    int v = mysum;
#pragma unroll
    for (int off = 1; off < 32; off <<= 1) {
        int u = __shfl_up_sync(0xffffffffu, v, off);
        if (lane >= off) v += u;
    }
    __shared__ int wsum[8];
    if (lane == 31) wsum[wid] = v;
    __syncthreads();
    if (wid == 0) {
        int w = (lane < 8) ? wsum[lane] : 0;
#pragma unroll
        for (int off = 1; off < 8; off <<= 1) {
            int u = __shfl_up_sync(0xffffffffu, w, off);
            if (lane >= off) w += u;
        }
        if (lane < 8) wsum[lane] = w;
    }
    __syncthreads();
    int excl = v - mysum + ((wid > 0) ? wsum[wid - 1] : 0);

    if (idx0 + 0 < NN) g_rowptr[idx0 + 0] = excl;
    if (idx0 + 1 < NN) g_rowptr[idx0 + 1] = excl + c0;
    if (idx0 + 2 < NN) g_rowptr[idx0 + 2] = excl + c0 + c1;
    if (idx0 + 3 < NN) g_rowptr[idx0 + 3] = excl + c0 + c1 + c2;

    if (tid == 255) g_partial[blockIdx.x] = excl + mysum;
}

__global__ void k_scan2() {
    const int lane = threadIdx.x;
    __shared__ int sh[64];
    sh[lane] = (lane < SCAN_BLOCKS) ? g_partial[lane] : 0;
    __syncthreads();
    if (lane == 0) {
        int run = 0;
        for (int i = 0; i < SCAN_BLOCKS; i++) { int c = sh[i]; sh[i] = run; run += c; }
    }
    __syncthreads();
    if (lane < SCAN_BLOCKS) g_partial[lane] = sh[lane];
}

__global__ __launch_bounds__(256) void k_scan3() {
    const int base = blockIdx.x * SCAN_CHUNK;
    const int off = g_partial[blockIdx.x];
    int i = base + threadIdx.x * 4;
#pragma unroll
    for (int j = 0; j < 4; j++)
        if (i + j < NN) g_rowptr[i + j] += off;
}

// build CSR: src index + precomputed norm = dinv[src]*w*dinv[dst]
__global__ void k_scatter(const int* __restrict__ ei, const float* __restrict__ ea) {
    int e = blockIdx.x * blockDim.x + threadIdx.x;
    if (e >= EE) return;
    int s = ei[e];
    int d = ei[EE + e];
    float w = ea[e];
    int pos = g_rowptr[d] + atomicAdd(&g_fill[d], 1);
    g_csrc[pos]  = s;
    g_cnorm[pos] = g_dinv[s] * w * g_dinv[d];
}

// layer-1: scalar aggregation (input dim = 1), plus per-graph node counts
__global__ void k_l1_agg(const float* __restrict__ x, const int* __restrict__ batch) {
    int n = blockIdx.x * blockDim.x + threadIdx.x;
    if (n >= NN) return;
    int beg = g_rowptr[n], end = beg + g_cnt[n];
    float acc = 0.f;
    for (int e = beg; e < end; e++)
        acc += g_cnorm[e] * __ldg(&x[g_csrc[e]]);
    acc += g_dinv2[n] * x[n];
    g_s[n] = acc;
    atomicAdd(&g_gcnt[batch[n]], 1);
}

// layer-1: h1[n,f] = relu(bn(s[n]*W1[f]+b1[f])) -> fp16
__global__ void k_l1h(const float* __restrict__ W1, const float* __restrict__ b1,
                      const float* __restrict__ g1, const float* __restrict__ be1,
                      const float* __restrict__ m1, const float* __restrict__ v1) {
    int idx = blockIdx.x * blockDim.x + threadIdx.x;
    if (idx >= NN * 64) return;
    int f = idx & 63;
    int n = idx >> 6;
    float sc = g1[f] * rsqrtf(v1[f] + BN_EPS);
    float sh = be1[f] - m1[f] * sc;
    float a = W1[f] * sc;
    float c = fmaf(b1[f], sc, sh);
    g_h1h[idx] = __float2half(fmaxf(fmaf(g_s[n], a, c), 0.f));
}

// ---------------- tensor-core GEMM: t[N,128] = A[N,K] @ W[K,128] ----------------
// A fp16 row-major, W pre-transposed fp16 [n][k]. fp32 accum via mma.sync m16n8k16.
// Block: 128 threads (4 warps), 64 nodes. K chunked by 64 in smem. Output fp16 g_t.
#define APITCH 72   // halves; 144B row pitch -> conflict-free fragment loads

template<int K>
__global__ __launch_bounds__(128) void k_gemm_mma() {
    const __half* __restrict__ A  = (K == 64) ? g_h1h : g_h2h;
    const __half* __restrict__ Wt = (K == 64) ? g_wt2 : g_wt3;

    __shared__ __half Ash[64 * APITCH];
    __shared__ __half Wsh[128 * APITCH];

    const int tid = threadIdx.x;
    const int lane = tid & 31;
    const int warp = tid >> 5;
    const int nb = blockIdx.x * 64;
    const int qr = lane >> 2;      // quad row 0..7
    const int qc = lane & 3;       // quad col 0..3

    float acc[16][4];
#pragma unroll
    for (int nt = 0; nt < 16; nt++) {
        acc[nt][0] = acc[nt][1] = acc[nt][2] = acc[nt][3] = 0.f;
    }

    for (int kk = 0; kk < K; kk += 64) {
        __syncthreads();
        // A tile: 64 rows x 64 halves (uint4 = 8 halves)
        for (int i = tid; i < 64 * 8; i += 128) {
            int row = i >> 3, seg = i & 7;
            int n = nb + row;
            uint4 v = make_uint4(0u, 0u, 0u, 0u);
            if (n < NN) v = *(const uint4*)&A[n * K + kk + seg * 8];
            *(uint4*)&Ash[row * APITCH + seg * 8] = v;
        }
        // W tile: 128 rows x 64 halves
        for (int i = tid; i < 128 * 8; i += 128) {
            int row = i >> 3, seg = i & 7;
            *(uint4*)&Wsh[row * APITCH + seg * 8] =
                *(const uint4*)&Wt[row * K + kk + seg * 8];
        }
        __syncthreads();

        const int m0 = warp * 16;
#pragma unroll
        for (int ks = 0; ks < 4; ks++) {
            const int k0 = ks * 16;
            unsigned a0 = *(const unsigned*)&Ash[(m0 + qr) * APITCH + k0 + qc * 2];
            unsigned a1 = *(const unsigned*)&Ash[(m0 + qr + 8) * APITCH + k0 + qc * 2];
            unsigned a2 = *(const unsigned*)&Ash[(m0 + qr) * APITCH + k0 + qc * 2 + 8];
            unsigned a3 = *(const unsigned*)&Ash[(m0 + qr + 8) * APITCH + k0 + qc * 2 + 8];
#pragma unroll
            for (int nt = 0; nt < 16; nt++) {
                unsigned b0 = *(const unsigned*)&Wsh[(nt * 8 + qr) * APITCH + k0 + qc * 2];
                unsigned b1 = *(const unsigned*)&Wsh[(nt * 8 + qr) * APITCH + k0 + qc * 2 + 8];
                asm volatile(
                    "mma.sync.aligned.m16n8k16.row.col.f32.f16.f16.f32 "
                    "{%0,%1,%2,%3}, {%4,%5,%6,%7}, {%8,%9}, {%0,%1,%2,%3};"
                    : "+f"(acc[nt][0]), "+f"(acc[nt][1]),
                      "+f"(acc[nt][2]), "+f"(acc[nt][3])
                    : "r"(a0), "r"(a1), "r"(a2), "r"(a3), "r"(b0), "r"(b1));
            }
        }
    }

    // epilogue: fp32 acc -> fp16 g_t
    const int m0 = warp * 16;
    const int r0 = nb + m0 + qr;
    const int r1 = r0 + 8;
#pragma unroll
    for (int nt = 0; nt < 16; nt++) {
        int ncol = nt * 8 + qc * 2;
        if (r0 < NN)
            *(__half2*)&g_t[r0 * 128 + ncol] = __floats2half2_rn(acc[nt][0], acc[nt][1]);
        if (r1 < NN)
            *(__half2*)&g_t[r1 * 128 + ncol] = __floats2half2_rn(acc[nt][2], acc[nt][3]);
    }
}

// ---------------- CSR gather (fp16 t), one warp per node ----------------
template<bool FINAL>
__global__ __launch_bounds__(256) void k_gather(
    const float* __restrict__ b, const float* __restrict__ g,
    const float* __restrict__ be, const float* __restrict__ m,
    const float* __restrict__ v, const float* __restrict__ Wf,
    const int* __restrict__ batch) {

    int wid = (blockIdx.x * blockDim.x + threadIdx.x) >> 5;
    int lane = threadIdx.x & 31;
    if (wid >= NN) return;
    int n = wid;

    int beg = g_rowptr[n], end = beg + g_cnt[n];
    float ax = 0.f, ay = 0.f, az = 0.f, aw = 0.f;
    for (int e = beg; e < end; e++) {
        int s = g_csrc[e];
        float nm = g_cnorm[e];
        uint2 raw = *(const uint2*)&g_t[s * 128 + lane * 4];
        float2 f0 = __half22float2(*(__half2*)&raw.x);
        float2 f1 = __half22float2(*(__half2*)&raw.y);
        ax = fmaf(nm, f0.x, ax);
        ay = fmaf(nm, f0.y, ay);
        az = fmaf(nm, f1.x, az);
        aw = fmaf(nm, f1.y, aw);
    }
    float di = g_dinv2[n];
    {
        uint2 raw = *(const uint2*)&g_t[n * 128 + lane * 4];
        float2 f0 = __half22float2(*(__half2*)&raw.x);
        float2 f1 = __half22float2(*(__half2*)&raw.y);
        ax = fmaf(di, f0.x, ax);
        ay = fmaf(di, f0.y, ay);
        az = fmaf(di, f1.x, az);
        aw = fmaf(di, f1.y, aw);
    }

    float4 b4  = *(const float4*)&b[lane * 4];
    float4 g4  = *(const float4*)&g[lane * 4];
    float4 be4 = *(const float4*)&be[lane * 4];
    float4 m4  = *(const float4*)&m[lane * 4];
    float4 v4  = *(const float4*)&v[lane * 4];

    float scx = g4.x * rsqrtf(v4.x + BN_EPS);
    float scy = g4.y * rsqrtf(v4.y + BN_EPS);
    float scz = g4.z * rsqrtf(v4.z + BN_EPS);
    float scw = g4.w * rsqrtf(v4.w + BN_EPS);
    float rx = fmaxf(fmaf(ax + b4.x - m4.x, scx, be4.x), 0.f);
    float ry = fmaxf(fmaf(ay + b4.y - m4.y, scy, be4.y), 0.f);
    float rz = fmaxf(fmaf(az + b4.z - m4.z, scz, be4.z), 0.f);
    float rw = fmaxf(fmaf(aw + b4.w - m4.w, scw, be4.w), 0.f);

    if (FINAL) {
        // residual from fp16 h2
        uint2 rr = *(const uint2*)&g_h2h[n * 128 + lane * 4];
        float2 q0 = __half22float2(*(__half2*)&rr.x);
        float2 q1 = __half22float2(*(__half2*)&rr.y);
        rx += q0.x; ry += q0.y; rz += q1.x; rw += q1.y;
        float4 wf = *(const float4*)&Wf[lane * 4];
        float y = rx * wf.x + ry * wf.y + rz * wf.z + rw * wf.w;
#pragma unroll
        for (int off = 16; off; off >>= 1) y += __shfl_xor_sync(0xffffffffu, y, off);
        if (lane == 0) atomicAdd(&g_gsum[batch[n]], y);
    } else {
        __half2 h0 = __floats2half2_rn(rx, ry);
        __half2 h1 = __floats2half2_rn(rz, rw);
        uint2 st;
        st.x = *(unsigned int*)&h0;
        st.y = *(unsigned int*)&h1;
        *(uint2*)&g_h2h[n * 128 + lane * 4] = st;
    }
}

__global__ void k_out(const float* __restrict__ bf, float* __restrict__ out) {
    int gidx = blockIdx.x * blockDim.x + threadIdx.x;
    if (gidx >= GG) return;
    out[gidx] = g_gsum[gidx] / fmaxf((float)g_gcnt[gidx], 1.f) + bf[0];
}

// ---------------- launch ----------------
extern "C" void kernel_launch(void* const* d_in, const int* in_sizes, int n_in,
                              void* d_out, int out_size) {
    const float* x   = (const float*)d_in[0];
    const int*   ei  = (const int*)d_in[1];
    const float* ea  = (const float*)d_in[2];
    const int*   bat = (const int*)d_in[3];
    const float* W1  = (const float*)d_in[4];
    const float* b1  = (const float*)d_in[5];
    const float* W2  = (const float*)d_in[6];
    const float* b2  = (const float*)d_in[7];
    const float* W3  = (const float*)d_in[8];
    const float* b3  = (const float*)d_in[9];
    const float* Wf  = (const float*)d_in[10];
    const float* bf  = (const float*)d_in[11];
    const float* g1  = (const float*)d_in[12];
    const float* be1 = (const float*)d_in[13];
    const float* m1  = (const float*)d_in[14];
    const float* v1  = (const float*)d_in[15];
    const float* g2  = (const float*)d_in[16];
    const float* be2 = (const float*)d_in[17];
    const float* m2  = (const float*)d_in[18];
    const float* v2  = (const float*)d_in[19];
    const float* g3  = (const float*)d_in[20];
    const float* be3 = (const float*)d_in[21];
    const float* m3  = (const float*)d_in[22];
    const float* v3  = (const float*)d_in[23];
    float* out = (float*)d_out;

    k_zero<<<(NN + 255) / 256, 256>>>();
    k_deg<<<(EE + 255) / 256, 256>>>(ei, ea);
    k_prep_w<<<(128 * 128 + 255) / 256, 256>>>(W2, W3);
    k_dinv<<<(NN + 255) / 256, 256>>>();
    k_scan1<<<SCAN_BLOCKS, 256>>>();
    k_scan2<<<1, 64>>>();
    k_scan3<<<SCAN_BLOCKS, 256>>>();
    k_scatter<<<(EE + 255) / 256, 256>>>(ei, ea);

    k_l1_agg<<<(NN + 255) / 256, 256>>>(x, bat);
    k_l1h<<<(NN * 64 + 255) / 256, 256>>>(W1, b1, g1, be1, m1, v1);

    k_gemm_mma<64><<<(NN + 63) / 64, 128>>>();
    k_gather<false><<<(NN * 32 + 255) / 256, 256>>>(b2, g2, be2, m2, v2, Wf, bat);

    k_gemm_mma<128><<<(NN + 63) / 64, 128>>>();
    k_gather<true><<<(NN * 32 + 255) / 256, 256>>>(b3, g3, be3, m3, v3, Wf, bat);

    k_out<<<(GG + 255) / 256, 256>>>(bf, out);
}

// round 5
// speedup vs baseline: 2.5279x; 1.0818x over previous
#include <cuda_runtime.h>
#include <cuda_fp16.h>

#define NN 50000
#define EE 640000
#define GG 500
#define BN_EPS 1e-5f

#define SCAN_CHUNK 1024
#define SCAN_BLOCKS ((NN + SCAN_CHUNK - 1) / SCAN_CHUNK)   // 49

// ---------------- scratch (static device globals; no allocation) ----------------
static __device__ __align__(16) float  g_deg[NN];
static __device__ __align__(16) float  g_dinv[NN];
static __device__ __align__(16) float  g_dinv2[NN];
static __device__ __align__(16) int    g_cnt[NN];
static __device__ __align__(16) int    g_rowptr[NN];     // local-exclusive within 1024-chunk
static __device__ __align__(16) int    g_fill[NN];
static __device__ __align__(16) int    g_partial[SCAN_BLOCKS];
static __device__ __align__(16) int    g_pscan[SCAN_BLOCKS];
static __device__ int                  g_ctr;
static __device__ __align__(16) int2   g_edge[EE];        // {src, norm-as-int}
static __device__ __align__(16) __half g_h1h[NN * 64];    // fp16 layer-1 output
static __device__ __align__(16) __half g_t[NN * 128];     // fp16 transformed features
static __device__ __align__(16) __half g_h2h[NN * 128];   // fp16 layer-2 output
static __device__ __align__(16) __half g_wt2[128 * 64];   // W2^T fp16 [n][k]
static __device__ __align__(16) __half g_wt3[128 * 128];  // W3^T fp16 [n][k]
static __device__ __align__(16) float  g_gsum[GG];
static __device__ __align__(16) int    g_gcnt[GG];

// ---------------- init: zero scratch + transpose/convert weights ----------------
__global__ void k_init(const float* __restrict__ W2, const float* __restrict__ W3) {
    int i = blockIdx.x * blockDim.x + threadIdx.x;
    if (i < NN) { g_deg[i] = 0.f; g_cnt[i] = 0; g_fill[i] = 0; }
    if (i < GG) { g_gsum[i] = 0.f; g_gcnt[i] = 0; }
    if (i == 0) g_ctr = 0;
    if (i < 128 * 64) {
        int n = i / 64, k = i % 64;
        g_wt2[i] = __float2half(W2[k * 128 + n]);
    }
    if (i < 128 * 128) {
        int n = i / 128, k = i % 128;
        g_wt3[i] = __float2half(W3[k * 128 + n]);
    }
}

__global__ void k_deg(const int* __restrict__ ei, const float* __restrict__ ea) {
    int e = blockIdx.x * blockDim.x + threadIdx.x;
    if (e >= EE) return;
    int d = ei[EE + e];
    atomicAdd(&g_deg[d], ea[e]);
    atomicAdd(&g_cnt[d], 1);
}

// ---- fused: per-chunk exclusive scan of cnt + dinv/dinv2 + last-block partial scan ----
__global__ __launch_bounds__(256) void k_scan(ulonglong1 /*dummy*/) {
    const int tid = threadIdx.x;
    const int base = blockIdx.x * SCAN_CHUNK;
    int idx0 = base + tid * 4;
    int c0 = 0, c1 = 0, c2 = 0, c3 = 0;
    if (idx0 + 0 < NN) c0 = g_cnt[idx0 + 0];
    if (idx0 + 1 < NN) c1 = g_cnt[idx0 + 1];
    if (idx0 + 2 < NN) c2 = g_cnt[idx0 + 2];
    if (idx0 + 3 < NN) c3 = g_cnt[idx0 + 3];
    int mysum = c0 + c1 + c2 + c3;

    // fused dinv for the same 4 nodes
#pragma unroll
    for (int j = 0; j < 4; j++) {
        int n = idx0 + j;
        if (n < NN) {
            float r = rsqrtf(g_deg[n] + 1.0f);
            g_dinv[n] = r;
            g_dinv2[n] = r * r;
        }
    }

    const int lane = tid & 31;
    const int wid = tid >> 5;
    int v = mysum;
#pragma unroll
    for (int off = 1; off < 32; off <<= 1) {
        int u = __shfl_up_sync(0xffffffffu, v, off);
        if (lane >= off) v += u;
    }
    __shared__ int wsum[8];
    if (lane == 31) wsum[wid] = v;
    __syncthreads();
    if (wid == 0) {
        int w = (lane < 8) ? wsum[lane] : 0;
#pragma unroll
        for (int off = 1; off < 8; off <<= 1) {
            int u = __shfl_up_sync(0xffffffffu, w, off);
            if (lane >= off) w += u;
        }
        if (lane < 8) wsum[lane] = w;
    }
    __syncthreads();
    int excl = v - mysum + ((wid > 0) ? wsum[wid - 1] : 0);

    if (idx0 + 0 < NN) g_rowptr[idx0 + 0] = excl;
    if (idx0 + 1 < NN) g_rowptr[idx0 + 1] = excl + c0;
    if (idx0 + 2 < NN) g_rowptr[idx0 + 2] = excl + c0 + c1;
    if (idx0 + 3 < NN) g_rowptr[idx0 + 3] = excl + c0 + c1 + c2;

    // last finishing block scans the partials
    if (tid == 255) {
        g_partial[blockIdx.x] = excl + mysum;
        __threadfence();
        int old = atomicAdd(&g_ctr, 1);
        if (old == SCAN_BLOCKS - 1) {
            __threadfence();
            int run = 0;
#pragma unroll 1
            for (int i = 0; i < SCAN_BLOCKS; i++) {
                int c = g_partial[i];
                g_pscan[i] = run;
                run += c;
            }
        }
    }
}

// build CSR: edge record {src, norm}, norm = dinv[src]*w*dinv[dst]
__global__ void k_scatter(const int* __restrict__ ei, const float* __restrict__ ea) {
    int e = blockIdx.x * blockDim.x + threadIdx.x;
    if (e >= EE) return;
    int s = ei[e];
    int d = ei[EE + e];
    float w = ea[e];
    int pos = g_rowptr[d] + g_pscan[d >> 10] + atomicAdd(&g_fill[d], 1);
    float nm = g_dinv[s] * w * g_dinv[d];
    g_edge[pos] = make_int2(s, __float_as_int(nm));
}

// layer-1 fused: scalar aggregation + BN/relu -> fp16 h1, + per-graph counts
__global__ __launch_bounds__(256) void k_l1(
    const float* __restrict__ x, const int* __restrict__ batch,
    const float* __restrict__ W1, const float* __restrict__ b1,
    const float* __restrict__ g1, const float* __restrict__ be1,
    const float* __restrict__ m1, const float* __restrict__ v1) {

    __shared__ float A1[64], C1[64];
    const int tid = threadIdx.x;
    if (tid < 64) {
        float sc = g1[tid] * rsqrtf(v1[tid] + BN_EPS);
        float sh = be1[tid] - m1[tid] * sc;
        A1[tid] = W1[tid] * sc;
        C1[tid] = fmaf(b1[tid], sc, sh);
    }
    __syncthreads();

    int n = blockIdx.x * blockDim.x + tid;
    if (n >= NN) return;
    int beg = g_rowptr[n] + g_pscan[n >> 10];
    int end = beg + g_cnt[n];
    float acc = 0.f;
    for (int e = beg; e < end; e++) {
        int2 ed = g_edge[e];
        acc = fmaf(__int_as_float(ed.y), __ldg(&x[ed.x]), acc);
    }
    acc = fmaf(g_dinv2[n], x[n], acc);

    atomicAdd(&g_gcnt[batch[n]], 1);

    // 64 features -> 8 uint4 stores (128B contiguous per thread)
    __half* dst = &g_h1h[n * 64];
#pragma unroll
    for (int f8 = 0; f8 < 64; f8 += 8) {
        uint4 pack;
        unsigned* pw = (unsigned*)&pack;
#pragma unroll
        for (int j = 0; j < 4; j++) {
            int f = f8 + j * 2;
            float u0 = fmaxf(fmaf(acc, A1[f], C1[f]), 0.f);
            float u1 = fmaxf(fmaf(acc, A1[f + 1], C1[f + 1]), 0.f);
            __half2 h = __floats2half2_rn(u0, u1);
            pw[j] = *(unsigned*)&h;
        }
        *(uint4*)&dst[f8] = pack;
    }
}

// ---------------- tensor-core GEMM: t[N,128] = A[N,K] @ W[K,128] ----------------
#define APITCH 72   // halves; 144B row pitch -> conflict-free fragment loads

template<int K>
__global__ __launch_bounds__(128) void k_gemm_mma() {
    const __half* __restrict__ A  = (K == 64) ? g_h1h : g_h2h;
    const __half* __restrict__ Wt = (K == 64) ? g_wt2 : g_wt3;

    __shared__ __half Ash[64 * APITCH];
    __shared__ __half Wsh[128 * APITCH];

    const int tid = threadIdx.x;
    const int lane = tid & 31;
    const int warp = tid >> 5;
    const int nb = blockIdx.x * 64;
    const int qr = lane >> 2;
    const int qc = lane & 3;

    float acc[16][4];
#pragma unroll
    for (int nt = 0; nt < 16; nt++) {
        acc[nt][0] = acc[nt][1] = acc[nt][2] = acc[nt][3] = 0.f;
    }

    for (int kk = 0; kk < K; kk += 64) {
        __syncthreads();
        for (int i = tid; i < 64 * 8; i += 128) {
            int row = i >> 3, seg = i & 7;
            int n = nb + row;
            uint4 v = make_uint4(0u, 0u, 0u, 0u);
            if (n < NN) v = *(const uint4*)&A[n * K + kk + seg * 8];
            *(uint4*)&Ash[row * APITCH + seg * 8] = v;
        }
        for (int i = tid; i < 128 * 8; i += 128) {
            int row = i >> 3, seg = i & 7;
            *(uint4*)&Wsh[row * APITCH + seg * 8] =
                *(const uint4*)&Wt[row * K + kk + seg * 8];
        }
        __syncthreads();

        const int m0 = warp * 16;
#pragma unroll
        for (int ks = 0; ks < 4; ks++) {
            const int k0 = ks * 16;
            unsigned a0 = *(const unsigned*)&Ash[(m0 + qr) * APITCH + k0 + qc * 2];
            unsigned a1 = *(const unsigned*)&Ash[(m0 + qr + 8) * APITCH + k0 + qc * 2];
            unsigned a2 = *(const unsigned*)&Ash[(m0 + qr) * APITCH + k0 + qc * 2 + 8];
            unsigned a3 = *(const unsigned*)&Ash[(m0 + qr + 8) * APITCH + k0 + qc * 2 + 8];
#pragma unroll
            for (int nt = 0; nt < 16; nt++) {
                unsigned b0 = *(const unsigned*)&Wsh[(nt * 8 + qr) * APITCH + k0 + qc * 2];
                unsigned b1 = *(const unsigned*)&Wsh[(nt * 8 + qr) * APITCH + k0 + qc * 2 + 8];
                asm volatile(
                    "mma.sync.aligned.m16n8k16.row.col.f32.f16.f16.f32 "
                    "{%0,%1,%2,%3}, {%4,%5,%6,%7}, {%8,%9}, {%0,%1,%2,%3};"
                    : "+f"(acc[nt][0]), "+f"(acc[nt][1]),
                      "+f"(acc[nt][2]), "+f"(acc[nt][3])
                    : "r"(a0), "r"(a1), "r"(a2), "r"(a3), "r"(b0), "r"(b1));
            }
        }
    }

    const int m0 = warp * 16;
    const int r0 = nb + m0 + qr;
    const int r1 = r0 + 8;
#pragma unroll
    for (int nt = 0; nt < 16; nt++) {
        int ncol = nt * 8 + qc * 2;
        if (r0 < NN)
            *(__half2*)&g_t[r0 * 128 + ncol] = __floats2half2_rn(acc[nt][0], acc[nt][1]);
        if (r1 < NN)
            *(__half2*)&g_t[r1 * 128 + ncol] = __floats2half2_rn(acc[nt][2], acc[nt][3]);
    }
}

// ---------------- CSR gather: 2 nodes per warp, 16 lanes x 8 features ----------------
__device__ __forceinline__ void acc8(float* a, uint4 raw, float nm) {
    float2 f0 = __half22float2(*(__half2*)&raw.x);
    float2 f1 = __half22float2(*(__half2*)&raw.y);
    float2 f2 = __half22float2(*(__half2*)&raw.z);
    float2 f3 = __half22float2(*(__half2*)&raw.w);
    a[0] = fmaf(nm, f0.x, a[0]); a[1] = fmaf(nm, f0.y, a[1]);
    a[2] = fmaf(nm, f1.x, a[2]); a[3] = fmaf(nm, f1.y, a[3]);
    a[4] = fmaf(nm, f2.x, a[4]); a[5] = fmaf(nm, f2.y, a[5]);
    a[6] = fmaf(nm, f3.x, a[6]); a[7] = fmaf(nm, f3.y, a[7]);
}

template<bool FINAL>
__global__ __launch_bounds__(256) void k_gather(
    const float* __restrict__ b, const float* __restrict__ g,
    const float* __restrict__ be, const float* __restrict__ m,
    const float* __restrict__ v, const float* __restrict__ Wf,
    const int* __restrict__ batch) {

    __shared__ float s_sc[128], s_sh[128], s_wf[128];
    const int tid = threadIdx.x;
    if (tid < 128) {
        float sc = g[tid] * rsqrtf(v[tid] + BN_EPS);
        s_sc[tid] = sc;
        s_sh[tid] = fmaf(b[tid] - m[tid], sc, be[tid]);
        if (FINAL) s_wf[tid] = Wf[tid];
    }
    __syncthreads();

    int hw = (blockIdx.x * blockDim.x + tid) >> 4;   // half-warp id = node
    int lane16 = tid & 15;
    if (hw >= NN) return;
    int n = hw;

    int beg = g_rowptr[n] + g_pscan[n >> 10];
    int end = beg + g_cnt[n];

    float a[8];
#pragma unroll
    for (int i = 0; i < 8; i++) a[i] = 0.f;

    const int fo = lane16 * 8;
    int e = beg;
    for (; e + 2 <= end; e += 2) {
        int2 e0 = g_edge[e];
        int2 e1 = g_edge[e + 1];
        uint4 r0 = *(const uint4*)&g_t[e0.x * 128 + fo];
        uint4 r1 = *(const uint4*)&g_t[e1.x * 128 + fo];
        acc8(a, r0, __int_as_float(e0.y));
        acc8(a, r1, __int_as_float(e1.y));
    }
    if (e < end) {
        int2 e0 = g_edge[e];
        uint4 r0 = *(const uint4*)&g_t[e0.x * 128 + fo];
        acc8(a, r0, __int_as_float(e0.y));
    }
    {
        uint4 rs = *(const uint4*)&g_t[n * 128 + fo];
        acc8(a, rs, g_dinv2[n]);
    }

    float r[8];
#pragma unroll
    for (int i = 0; i < 8; i++)
        r[i] = fmaxf(fmaf(a[i], s_sc[fo + i], s_sh[fo + i]), 0.f);

    if (FINAL) {
        uint4 rr = *(const uint4*)&g_h2h[n * 128 + fo];
        float2 q0 = __half22float2(*(__half2*)&rr.x);
        float2 q1 = __half22float2(*(__half2*)&rr.y);
        float2 q2 = __half22float2(*(__half2*)&rr.z);
        float2 q3 = __half22float2(*(__half2*)&rr.w);
        r[0] += q0.x; r[1] += q0.y; r[2] += q1.x; r[3] += q1.y;
        r[4] += q2.x; r[5] += q2.y; r[6] += q3.x; r[7] += q3.y;
        float y = 0.f;
#pragma unroll
        for (int i = 0; i < 8; i++) y = fmaf(r[i], s_wf[fo + i], y);
#pragma unroll
        for (int off = 8; off; off >>= 1) y += __shfl_xor_sync(0xffffffffu, y, off);
        if (lane16 == 0) atomicAdd(&g_gsum[batch[n]], y);
    } else {
        uint4 pack;
        unsigned* pw = (unsigned*)&pack;
#pragma unroll
        for (int j = 0; j < 4; j++) {
            __half2 h = __floats2half2_rn(r[j * 2], r[j * 2 + 1]);
            pw[j] = *(unsigned*)&h;
        }
        *(uint4*)&g_h2h[n * 128 + fo] = pack;
    }
}

__global__ void k_out(const float* __restrict__ bf, float* __restrict__ out) {
    int gidx = blockIdx.x * blockDim.x + threadIdx.x;
    if (gidx >= GG) return;
    out[gidx] = g_gsum[gidx] / fmaxf((float)g_gcnt[gidx], 1.f) + bf[0];
}

// ---------------- launch ----------------
extern "C" void kernel_launch(void* const* d_in, const int* in_sizes, int n_in,
                              void* d_out, int out_size) {
    const float* x   = (const float*)d_in[0];
    const int*   ei  = (const int*)d_in[1];
    const float* ea  = (const float*)d_in[2];
    const int*   bat = (const int*)d_in[3];
    const float* W1  = (const float*)d_in[4];
    const float* b1  = (const float*)d_in[5];
    const float* W2  = (const float*)d_in[6];
    const float* b2  = (const float*)d_in[7];
    const float* W3  = (const float*)d_in[8];
    const float* b3  = (const float*)d_in[9];
    const float* Wf  = (const float*)d_in[10];
    const float* bf  = (const float*)d_in[11];
    const float* g1  = (const float*)d_in[12];
    const float* be1 = (const float*)d_in[13];
    const float* m1  = (const float*)d_in[14];
    const float* v1  = (const float*)d_in[15];
    const float* g2  = (const float*)d_in[16];
    const float* be2 = (const float*)d_in[17];
    const float* m2  = (const float*)d_in[18];
    const float* v2  = (const float*)d_in[19];
    const float* g3  = (const float*)d_in[20];
    const float* be3 = (const float*)d_in[21];
    const float* m3  = (const float*)d_in[22];
    const float* v3  = (const float*)d_in[23];
    float* out = (float*)d_out;

    k_init<<<(NN + 255) / 256, 256>>>(W2, W3);
    k_deg<<<(EE + 255) / 256, 256>>>(ei, ea);
    k_scan<<<SCAN_BLOCKS, 256>>>(make_ulonglong1(0));
    k_scatter<<<(EE + 255) / 256, 256>>>(ei, ea);

    k_l1<<<(NN + 255) / 256, 256>>>(x, bat, W1, b1, g1, be1, m1, v1);

    k_gemm_mma<64><<<(NN + 63) / 64, 128>>>();
    k_gather<false><<<(NN * 16 + 255) / 256, 256>>>(b2, g2, be2, m2, v2, Wf, bat);

    k_gemm_mma<128><<<(NN + 63) / 64, 128>>>();
    k_gather<true><<<(NN * 16 + 255) / 256, 256>>>(b3, g3, be3, m3, v3, Wf, bat);

    k_out<<<(GG + 255) / 256, 256>>>(bf, out);
}